// round 6
// baseline (speedup 1.0000x reference)
#include <cuda_runtime.h>

// SpatialAwareFocalLoss — GB300 sm_103a, round 6.
// Empirical finding: kernel time is launch/latency dominated (all pipes <12%,
// flat across algorithms, best at grid=64). So: fewest CTAs (64), no load
// duplication (8 classes/thread), max MLP at entry (6 independent LDG),
// line-bin window (2 ATOMS + 10 LDS), exactly 3 barriers, single kernel.

static constexpr int S    = 1024;   // SEQ_LEN
static constexpr int NBIN = 262;    // bin idx = line + 2, lines 0..255
static constexpr int MAXB = 256;

__device__ float        g_part[MAXB];
__device__ unsigned int g_cnt = 0;

__global__ __launch_bounds__(1024, 1)
void focal_kernel(const float* __restrict__ pred,
                  const float* __restrict__ target,
                  const int*   __restrict__ token_to_line,
                  float* __restrict__ out,
                  float inv_total, int nblocks)
{
    __shared__ int   s_bin_i[NBIN];  // cnt + (tsum<<16)
    __shared__ float s_bin_f[NBIN];  // sigmoid sum (all 8 classes) per line
    __shared__ float s_red[32];

    const int b    = blockIdx.x;
    const int i    = threadIdx.x;
    const int lane = i & 31, warp = i >> 5;
    const long tok  = (long)b * S + i;
    const long base = tok * 8;

    // issue all 6 independent loads immediately (MLP=6)
    const int    li = __ldg(token_to_line + tok);
    const float4 pa = __ldg((const float4*)(pred + base));
    const float4 pb = __ldg((const float4*)(pred + base + 4));
    const float4 ta = __ldg((const float4*)(target + base));
    const float4 tb = __ldg((const float4*)(target + base + 4));

    if (i < NBIN) { s_bin_i[i] = 0; s_bin_f[i] = 0.0f; }

    float p[8] = {pa.x, pa.y, pa.z, pa.w, pb.x, pb.y, pb.z, pb.w};
    float t[8] = {ta.x, ta.y, ta.z, ta.w, tb.x, tb.y, tb.z, tb.w};

    float tsumf = 0.0f, sigsum = 0.0f, local = 0.0f;
    #pragma unroll
    for (int c = 0; c < 8; ++c) {
        const float x = p[c];
        const float e = __expf(-fabsf(x));
        const float a = 1.0f / (1.0f + e);        // sigmoid(|x|)
        const float g = e * a;                    // 1 - sigmoid(|x|)
        const float sig  = (x >= 0.0f) ? a : g;
        const float sig1 = (x >= 0.0f) ? g : a;   // 1 - sig
        sigsum += sig;
        tsumf  += t[c];
        const float pt  = (t[c] > 0.5f) ? sig : sig1;
        const float omp = (t[c] > 0.5f) ? sig1 : sig;   // 1 - pt
        const float bce = -__logf(pt);
        const float o2  = omp * omp;
        local += 0.01f * o2 * o2 * bce;           // ALPHA*(1-pt)^GAMMA*bce
    }

    __syncthreads();                              // barrier 1: bins zeroed

    const int self_i = 1 + ((int)tsumf << 16);
    atomicAdd(&s_bin_i[li + 2], self_i);
    atomicAdd(&s_bin_f[li + 2], sigsum);
    __syncthreads();                              // barrier 2: bins complete

    // window lines [li-2, li+2] = bins [li, li+4]; exclude self
    int   ci   = -self_i;
    float nsig = -sigsum;
    #pragma unroll
    for (int k = 0; k < 5; ++k) {
        ci   += s_bin_i[li + k];
        nsig += s_bin_f[li + k];
    }
    const int cnt  = ci & 0xffff;                 // neighbors excluding self
    const int ntgt = ci >> 16;                    // exact integer gate

    if (cnt > 0 && ntgt > 0)
        local += 0.03f * __fdividef(nsig, (float)cnt);

    // block reduction -> one partial per CTA
    #pragma unroll
    for (int o = 16; o > 0; o >>= 1)
        local += __shfl_xor_sync(0xffffffffu, local, o);
    if (lane == 0) s_red[warp] = local;
    __syncthreads();                              // barrier 3

    if (warp == 0) {
        float v = s_red[lane];
        #pragma unroll
        for (int o = 16; o > 0; o >>= 1)
            v += __shfl_xor_sync(0xffffffffu, v, o);

        unsigned int ticket = 0;
        if (lane == 0) {
            g_part[b] = v;
            __threadfence();
            ticket = atomicAdd(&g_cnt, 1u) + 1u;
        }
        ticket = __shfl_sync(0xffffffffu, ticket, 0);

        if ((int)ticket == nblocks) {             // last CTA: final reduce
            __threadfence();
            float acc = 0.0f;
            for (int k = lane; k < nblocks; k += 32)
                acc += __ldcg(&g_part[k]);
            #pragma unroll
            for (int o = 16; o > 0; o >>= 1)
                acc += __shfl_xor_sync(0xffffffffu, acc, o);
            if (lane == 0) {
                out[0] = acc * inv_total;
                g_cnt = 0;                        // reset for next graph replay
            }
        }
    }
}

extern "C" void kernel_launch(void* const* d_in, const int* in_sizes, int n_in,
                              void* d_out, int out_size)
{
    const float* pred   = (const float*)d_in[0];
    const float* target = (const float*)d_in[1];
    const int*   lines  = (const int*)d_in[2];
    float* out = (float*)d_out;

    const int BS = in_sizes[2];
    const int B  = BS / S;                        // 64 CTAs
    const float inv_total = 1.0f / ((float)BS * 8.0f);

    focal_kernel<<<B, 1024>>>(pred, target, lines, out, inv_total, B);
}

// round 7
// speedup vs baseline: 1.3026x; 1.3026x over previous
#include <cuda_runtime.h>

// SpatialAwareFocalLoss — GB300 sm_103a, round 7.
// R4 shape (grid=128: 2 CTAs/sequence, 4 classes each — empirically fastest,
// balances MUFU throughput vs load duplication) + slimmer tail:
// single global float accumulator instead of a 128-partial gather.

static constexpr int S    = 1024;   // SEQ_LEN
static constexpr int NBIN = 262;    // bin idx = line + 2, lines 0..255

__device__ float        g_accum = 0.0f;
__device__ unsigned int g_cnt   = 0;

__global__ __launch_bounds__(1024, 1)
void focal_kernel(const float* __restrict__ pred,
                  const float* __restrict__ target,
                  const int*   __restrict__ token_to_line,
                  float* __restrict__ out,
                  float inv_total, int nblocks)
{
    __shared__ int   s_bin_i[NBIN];  // cnt + (tsum<<16)
    __shared__ float s_bin_f[NBIN];  // this half's sigmoid sum per line
    __shared__ float s_red[32];

    const int bid  = blockIdx.x;
    const int b    = bid >> 1;        // sequence
    const int half = bid & 1;         // classes 0-3 or 4-7
    const int i    = threadIdx.x;
    const int lane = i & 31, warp = i >> 5;

    const long tok  = (long)b * S + i;
    const long base = tok * 8;

    // all independent loads issued up front (li gates the atomic phase)
    const int    li = __ldg(token_to_line + tok);
    const float4 p4 = __ldg((const float4*)(pred + base + half * 4));
    const float4 ta = __ldg((const float4*)(target + base));
    const float4 tb = __ldg((const float4*)(target + base + 4));

    if (i < NBIN) { s_bin_i[i] = 0; s_bin_f[i] = 0.0f; }

    // full-class token target sum (small integer, exact) -> window gate
    const int tint = (int)(ta.x + ta.y + ta.z + ta.w + tb.x + tb.y + tb.z + tb.w);

    const float4 ts = half ? tb : ta;
    float p[4] = {p4.x, p4.y, p4.z, p4.w};
    float t[4] = {ts.x, ts.y, ts.z, ts.w};

    float sigsum = 0.0f, local = 0.0f;
    #pragma unroll
    for (int c = 0; c < 4; ++c) {
        const float x = p[c];
        const float e = __expf(-fabsf(x));
        const float a = 1.0f / (1.0f + e);        // sigmoid(|x|)
        const float g = e * a;                    // 1 - sigmoid(|x|)
        const float sig  = (x >= 0.0f) ? a : g;
        const float sig1 = (x >= 0.0f) ? g : a;   // 1 - sig
        sigsum += sig;
        const float pt  = (t[c] > 0.5f) ? sig : sig1;
        const float omp = (t[c] > 0.5f) ? sig1 : sig;   // 1 - pt
        const float bce = -__logf(pt);
        const float o2  = omp * omp;
        local += 0.01f * o2 * o2 * bce;           // ALPHA*(1-pt)^GAMMA*bce
    }

    __syncthreads();                              // barrier 1: bins zeroed

    const int self_i = 1 + (tint << 16);
    atomicAdd(&s_bin_i[li + 2], self_i);
    atomicAdd(&s_bin_f[li + 2], sigsum);
    __syncthreads();                              // barrier 2: bins complete

    // window lines [li-2, li+2] -> bins [li, li+4]; exclude self
    int   ci   = -self_i;
    float nsig = -sigsum;
    #pragma unroll
    for (int k = 0; k < 5; ++k) {
        ci   += s_bin_i[li + k];
        nsig += s_bin_f[li + k];
    }
    const int cnt  = ci & 0xffff;                 // neighbors excluding self
    const int ntgt = ci >> 16;                    // exact integer gate

    if (cnt > 0 && ntgt > 0)
        local += 0.03f * __fdividef(nsig, (float)cnt);

    // block reduction
    #pragma unroll
    for (int o = 16; o > 0; o >>= 1)
        local += __shfl_xor_sync(0xffffffffu, local, o);
    if (lane == 0) s_red[warp] = local;
    __syncthreads();                              // barrier 3

    if (warp == 0) {
        float v = s_red[lane];
        #pragma unroll
        for (int o = 16; o > 0; o >>= 1)
            v += __shfl_xor_sync(0xffffffffu, v, o);

        unsigned int ticket = 0;
        if (lane == 0) {
            atomicAdd(&g_accum, v);               // single global accumulator
            __threadfence();
            ticket = atomicAdd(&g_cnt, 1u) + 1u;
        }
        ticket = __shfl_sync(0xffffffffu, ticket, 0);

        if ((int)ticket == nblocks && lane == 0) {    // last CTA finishes
            __threadfence();
            const float acc = *((volatile float*)&g_accum);
            out[0]  = acc * inv_total;
            g_accum = 0.0f;                       // reset for next replay
            g_cnt   = 0;
        }
    }
}

extern "C" void kernel_launch(void* const* d_in, const int* in_sizes, int n_in,
                              void* d_out, int out_size)
{
    const float* pred   = (const float*)d_in[0];
    const float* target = (const float*)d_in[1];
    const int*   lines  = (const int*)d_in[2];
    float* out = (float*)d_out;

    const int BS = in_sizes[2];
    const int B  = BS / S;
    const int nblocks = 2 * B;                    // 128 CTAs
    const float inv_total = 1.0f / ((float)BS * 8.0f);

    focal_kernel<<<nblocks, 1024>>>(pred, target, lines, out, inv_total, nblocks);
}

// round 8
// speedup vs baseline: 1.3074x; 1.0037x over previous
#include <cuda_runtime.h>

// SpatialAwareFocalLoss — GB300 sm_103a, round 8.
// R7 shape (grid=128, 2 CTAs/sequence, 4 classes each) + fused finish:
// one 64-bit atomic packs {count<<48 | fixed-point sum(2^32)} — the returned
// value gives the last CTA the complete total with no fence/counter/re-read.

static constexpr int S    = 1024;   // SEQ_LEN
static constexpr int NBIN = 262;    // bin idx = line + 2, lines 0..255

__device__ unsigned long long g_word = 0ULL;   // [63:48]=count, [47:0]=sum*2^32

__global__ __launch_bounds__(1024, 1)
void focal_kernel(const float* __restrict__ pred,
                  const float* __restrict__ target,
                  const int*   __restrict__ token_to_line,
                  float* __restrict__ out,
                  float inv_total, int nblocks)
{
    __shared__ int   s_bin_i[NBIN];  // cnt + (tsum<<16)
    __shared__ float s_bin_f[NBIN];  // this half's sigmoid sum per line
    __shared__ float s_red[32];

    const int bid  = blockIdx.x;
    const int b    = bid >> 1;        // sequence
    const int half = bid & 1;         // classes 0-3 or 4-7
    const int i    = threadIdx.x;
    const int lane = i & 31, warp = i >> 5;

    const long tok  = (long)b * S + i;
    const long base = tok * 8;

    // all independent loads issued up front (li gates the atomic phase)
    const int    li = __ldg(token_to_line + tok);
    const float4 p4 = __ldg((const float4*)(pred + base + half * 4));
    const float4 ta = __ldg((const float4*)(target + base));
    const float4 tb = __ldg((const float4*)(target + base + 4));

    if (i < NBIN) { s_bin_i[i] = 0; s_bin_f[i] = 0.0f; }

    // full-class token target sum (small integer, exact) -> window gate
    const int tint = (int)(ta.x + ta.y + ta.z + ta.w + tb.x + tb.y + tb.z + tb.w);

    const float4 ts = half ? tb : ta;
    float p[4] = {p4.x, p4.y, p4.z, p4.w};
    float t[4] = {ts.x, ts.y, ts.z, ts.w};

    float sigsum = 0.0f, local = 0.0f;
    #pragma unroll
    for (int c = 0; c < 4; ++c) {
        const float x = p[c];
        const float e = __expf(-fabsf(x));
        const float a = 1.0f / (1.0f + e);        // sigmoid(|x|)
        const float g = e * a;                    // 1 - sigmoid(|x|)
        const float sig  = (x >= 0.0f) ? a : g;
        const float sig1 = (x >= 0.0f) ? g : a;   // 1 - sig
        sigsum += sig;
        const float pt  = (t[c] > 0.5f) ? sig : sig1;
        const float omp = (t[c] > 0.5f) ? sig1 : sig;   // 1 - pt
        const float bce = -__logf(pt);
        const float o2  = omp * omp;
        local += 0.01f * o2 * o2 * bce;           // ALPHA*(1-pt)^GAMMA*bce
    }

    __syncthreads();                              // barrier 1: bins zeroed

    const int self_i = 1 + (tint << 16);
    atomicAdd(&s_bin_i[li + 2], self_i);
    atomicAdd(&s_bin_f[li + 2], sigsum);
    __syncthreads();                              // barrier 2: bins complete

    // window lines [li-2, li+2] -> bins [li, li+4]; exclude self
    int   ci   = -self_i;
    float nsig = -sigsum;
    #pragma unroll
    for (int k = 0; k < 5; ++k) {
        ci   += s_bin_i[li + k];
        nsig += s_bin_f[li + k];
    }
    const int cnt  = ci & 0xffff;                 // neighbors excluding self
    const int ntgt = ci >> 16;                    // exact integer gate

    if (cnt > 0 && ntgt > 0)
        local += 0.03f * __fdividef(nsig, (float)cnt);

    // block reduction
    #pragma unroll
    for (int o = 16; o > 0; o >>= 1)
        local += __shfl_xor_sync(0xffffffffu, local, o);
    if (lane == 0) s_red[warp] = local;
    __syncthreads();                              // barrier 3

    if (warp == 0) {
        float v = s_red[lane];
        #pragma unroll
        for (int o = 16; o > 0; o >>= 1)
            v += __shfl_xor_sync(0xffffffffu, v, o);

        if (lane == 0) {
            // v >= 0 (focal and penalty terms are non-negative)
            const unsigned long long fix =
                (unsigned long long)__double2ll_rn((double)v * 4294967296.0);
            const unsigned long long pack = (1ULL << 48) + fix;
            const unsigned long long old  = atomicAdd(&g_word, pack);

            if ((int)(old >> 48) == nblocks - 1) {      // we are the last CTA
                const unsigned long long tot =
                    (old + pack) & ((1ULL << 48) - 1ULL);
                out[0] = (float)((double)tot * (1.0 / 4294967296.0)
                                 * (double)inv_total);
                atomicExch(&g_word, 0ULL);              // reset for next replay
            }
        }
    }
}

extern "C" void kernel_launch(void* const* d_in, const int* in_sizes, int n_in,
                              void* d_out, int out_size)
{
    const float* pred   = (const float*)d_in[0];
    const float* target = (const float*)d_in[1];
    const int*   lines  = (const int*)d_in[2];
    float* out = (float*)d_out;

    const int BS = in_sizes[2];
    const int B  = BS / S;
    const int nblocks = 2 * B;                    // 128 CTAs
    const float inv_total = 1.0f / ((float)BS * 8.0f);

    focal_kernel<<<nblocks, 1024>>>(pred, target, lines, out, inv_total, nblocks);
}